// round 15
// baseline (speedup 1.0000x reference)
#include <cuda_runtime.h>

#define CIN   384
#define FEAT  192
#define CGATE 768
#define NB    16
#define NH    64
#define NW    64
#define NBLK  128     // persistent blocks: 16 batch-tiles x 8 gate-col tiles

#define SLAB_STRIDE 72
// dynamic smem layout (floats) for recurrence (768 threads, 3 k-groups):
//   slab : 192*72                 = 13824  (h_{y-1}[f][w] with halo, data at j=w+1)
//   Bsm  : 3 grp * 2 buf * 32*96  = 18432  (per-group double-buffered weight chunks)
//   Ss   : 3 grp * 96*68          = 19584  (per-group partial s tiles)
//   Cs   : 24*64                  =  1536  (cell state, persistent across rows)
#define SMEM_FLOATS (13824 + 18432 + 19584 + 1536)
#define SMEM_BYTES  (SMEM_FLOATS * 4)      // 213504 B

// ---------------- device scratch ----------------
__device__ float g_hpre[(size_t)NH * NB * NW * CGATE];  // [m][n'] n' = f*4 + gate
__device__ float g_outh[(size_t)NH * NB * FEAT * NW];   // [y][b][f][w]
__device__ float g_wA[CIN * 2 * CGATE];                 // i2s masked+shuffled, cols n'=f*4+q
__device__ float g_wR[FEAT * 3 * CGATE];                // s2s, rows k=kw*192+ci, cols n'=f*4+q
__device__ float g_wS[FEAT * CIN];                      // skip masked, [f][cin]
__device__ int   g_sync;                                // inter-block barrier counter

// ---------------- weight prep ----------------
__global__ void prep_weights(const float* __restrict__ w_i2s,
                             const float* __restrict__ w_s2s,
                             const float* __restrict__ w_skip) {
    int stride = gridDim.x * blockDim.x;
    int t0 = blockIdx.x * blockDim.x + threadIdx.x;
    if (t0 == 0) g_sync = 0;                       // reset barrier each launch

    // g_wA: [k=ci*2+tap][n'=f*4+q]; shuffled source channel cg = g*256 + q*64 + r
    for (int i = t0; i < CIN * 2 * CGATE; i += stride) {
        int k = i / CGATE, np = i % CGATE;
        int ci = k >> 1, tap = k & 1;
        int q = np & 3, f = np >> 2;
        int g = f >> 6, r = f & 63;
        int cg = g * 256 + q * 64 + r;
        float v = w_i2s[(cg * CIN + ci) * 3 + tap];
        if (tap == 1 && g < (ci >> 7)) v = 0.f;    // center tap mask; right tap dropped
        g_wA[i] = v;
    }
    // g_wR: [k=kw*192+ci][n'=f*4+q]
    for (int i = t0; i < FEAT * 3 * CGATE; i += stride) {
        int k = i / CGATE, np = i % CGATE;
        int kw = k / 192, ci = k - kw * 192;
        int q = np & 3, f = np >> 2;
        g_wR[i] = w_s2s[((q * 192 + f) * FEAT + ci) * 3 + kw];
    }
    // g_wS: masked 1x1 skip, transposed to [f][cin]
    for (int i = t0; i < FEAT * CIN; i += stride) {
        int f = i / CIN, c = i % CIN;
        g_wS[i] = ((c >> 7) >= (f >> 6)) ? w_skip[c * FEAT + f] : 0.f;
    }
}

// ---------------- phase 1: input conv GEMM, BM=128 BN=128 BK=16, 8x8 tiles ----------------
__global__ __launch_bounds__(256) void phase1_gemm(const float* __restrict__ x) {
    __shared__ float As[16][128];
    __shared__ float Bs[16][128];
    const int m0 = blockIdx.x * 128;
    const int n0 = blockIdx.y * 128;
    const int tid = threadIdx.x;
    const int tx = tid & 15;   // n: owns n0 + tx*8 .. +7
    const int ty = tid >> 4;   // m: owns m0 + ty*8 .. +7

    float acc[8][8];
#pragma unroll
    for (int i = 0; i < 8; i++)
#pragma unroll
        for (int j = 0; j < 8; j++) acc[i][j] = 0.f;

    for (int k0 = 0; k0 < CIN * 2; k0 += 16) {
#pragma unroll
        for (int i = 0; i < 8; i++) {
            int idx = tid + i * 256;
            int kk = idx >> 7, mm = idx & 127;
            int m = m0 + mm;
            int w = m & 63, b = (m >> 6) & 15, y = m >> 10;
            int kg = k0 + kk;
            int ci = kg >> 1, tap = kg & 1;
            int xw = w + tap - 1;
            float v = 0.f;
            if (xw >= 0) v = x[((b * CIN + ci) * NH + y) * NW + xw];
            As[kk][mm] = v;
        }
#pragma unroll
        for (int r = 0; r < 2; r++) {
            int lin = tid + r * 256;
            int kk = lin >> 5, nn4 = lin & 31;
            *(float4*)&Bs[kk][nn4 * 4] =
                *(const float4*)&g_wA[(size_t)(k0 + kk) * CGATE + n0 + nn4 * 4];
        }
        __syncthreads();
#pragma unroll
        for (int k = 0; k < 16; k++) {
            float4 a0 = *(const float4*)&As[k][ty * 8];
            float4 a1 = *(const float4*)&As[k][ty * 8 + 4];
            float4 b0 = *(const float4*)&Bs[k][tx * 8];
            float4 b1 = *(const float4*)&Bs[k][tx * 8 + 4];
            float a[8] = {a0.x, a0.y, a0.z, a0.w, a1.x, a1.y, a1.z, a1.w};
            float b[8] = {b0.x, b0.y, b0.z, b0.w, b1.x, b1.y, b1.z, b1.w};
#pragma unroll
            for (int i = 0; i < 8; i++)
#pragma unroll
                for (int j = 0; j < 8; j++)
                    acc[i][j] = fmaf(a[i], b[j], acc[i][j]);
        }
        __syncthreads();
    }
#pragma unroll
    for (int i = 0; i < 8; i++) {
        int m = m0 + ty * 8 + i;
        float* dst = &g_hpre[(size_t)m * CGATE + n0 + tx * 8];
        *(float4*)dst       = make_float4(acc[i][0], acc[i][1], acc[i][2], acc[i][3]);
        *(float4*)(dst + 4) = make_float4(acc[i][4], acc[i][5], acc[i][6], acc[i][7]);
    }
}

// ---------------- phase 2: persistent fused recurrence, 768 thr, K-split x3 ----------------
__device__ __forceinline__ float sigm(float v) { return 1.f / (1.f + __expf(-v)); }

__global__ __launch_bounds__(768, 1) void recurrence() {
    extern __shared__ float sm[];
    float* slab = sm;                       // 192 x 72
    float* Bsm  = sm + 13824;               // 3 grp x 2 buf x 3072
    float* Ss   = sm + 13824 + 18432;       // 3 grp x 6528
    float* Cs   = sm + 13824 + 18432 + 19584; // 24 x 64

    const int tid = threadIdx.x;
    const int grp = tid >> 8;               // k-split group 0..2 == its conv tap kw
    const int t2  = tid & 255;
    const int tx  = t2 & 15;                // m-lane: owns m = tx + 16*i
    const int ty  = t2 >> 4;                // n-lane: owns n' = ty*6 .. +5
    const int bm  = blockIdx.x & 15;        // batch b
    const int bn  = blockIdx.x >> 4;        // 0..7, n0 = bn*96
    const int n0  = bn * 96;

    float* myB  = Bsm + grp * 6144;
    float* mySs = Ss + grp * 6528;

    // one-time init (first use is after a __syncthreads)
    for (int p = tid; p < 1536; p += 768) Cs[p] = 0.f;
    if (tid < 192) { slab[tid * SLAB_STRIDE] = 0.f; slab[tid * SLAB_STRIDE + 65] = 0.f; }

    for (int y = 0; y < NH; y++) {
        // group 0 prefetches hpre tile into regs (added at its Ss write)
        float pre[6][4];
        if (grp == 0) {
            size_t mb = (size_t)(y * NB + bm) * NW;
#pragma unroll
            for (int i = 0; i < 4; i++) {
                const float* p = &g_hpre[(mb + tx + i * 16) * CGATE + n0 + ty * 6];
                float2 v0 = *(const float2*)(p);
                float2 v1 = *(const float2*)(p + 2);
                float2 v2 = *(const float2*)(p + 4);
                pre[0][i] = v0.x; pre[1][i] = v0.y;
                pre[2][i] = v1.x; pre[3][i] = v1.y;
                pre[4][i] = v2.x; pre[5][i] = v2.y;
            }
        }

        float acc[6][4];
#pragma unroll
        for (int j = 0; j < 6; j++)
#pragma unroll
            for (int i = 0; i < 4; i++) acc[j][i] = 0.f;

        if (y > 0) {
            // slab: h_{y-1}[192][64] into smem (768 threads, 4 float4 each)
            const float* hp = &g_outh[(size_t)((y - 1) * NB + bm) * FEAT * NW];
#pragma unroll
            for (int r = 0; r < 4; r++) {
                int lin = tid + r * 768;            // float4 index 0..3071
                int f = lin >> 4;
                int w4 = (lin & 15) << 2;
                float4 v = *(const float4*)&hp[f * NW + w4];
                float* d = &slab[f * SLAB_STRIDE + 1 + w4];
                d[0] = v.x; d[1] = v.y; d[2] = v.z; d[3] = v.w;
            }
            // preload my group's first chunk (global chunk grp*6)
            float4 bfr[3];
#pragma unroll
            for (int r = 0; r < 3; r++) {
                int lin = t2 + r * 256;             // 0..767 float4
                int kk = lin / 24;
                int nn = (lin % 24) << 2;
                bfr[r] = *(const float4*)&g_wR[(size_t)(grp * 6 * 32 + kk) * CGATE + n0 + nn];
            }
#pragma unroll
            for (int r = 0; r < 3; r++) {
                int lin = t2 + r * 256;
                int kk = lin / 24;
                int nn = (lin % 24) << 2;
                *(float4*)&myB[kk * 96 + nn] = bfr[r];
            }
            __syncthreads();

            // group's 6 chunks all share tap kw == grp -> A base fixed per group
            for (int c = 0; c < 6; c++) {
                if (c < 5) {                        // prefetch next chunk
#pragma unroll
                    for (int r = 0; r < 3; r++) {
                        int lin = t2 + r * 256;
                        int kk = lin / 24;
                        int nn = (lin % 24) << 2;
                        bfr[r] = *(const float4*)&g_wR[(size_t)((grp * 6 + c + 1) * 32 + kk) * CGATE + n0 + nn];
                    }
                }
                const float* aP = &slab[(c * 32) * SLAB_STRIDE + tx + grp];
                const float* bP = &myB[(c & 1) * 3072 + ty * 6];
#pragma unroll
                for (int kk = 0; kk < 32; kk++) {
                    float a0 = aP[kk * SLAB_STRIDE + 0];
                    float a1 = aP[kk * SLAB_STRIDE + 16];
                    float a2 = aP[kk * SLAB_STRIDE + 32];
                    float a3 = aP[kk * SLAB_STRIDE + 48];
                    float2 b01 = *(const float2*)&bP[kk * 96 + 0];
                    float2 b23 = *(const float2*)&bP[kk * 96 + 2];
                    float2 b45 = *(const float2*)&bP[kk * 96 + 4];
                    acc[0][0] = fmaf(a0, b01.x, acc[0][0]);
                    acc[0][1] = fmaf(a1, b01.x, acc[0][1]);
                    acc[0][2] = fmaf(a2, b01.x, acc[0][2]);
                    acc[0][3] = fmaf(a3, b01.x, acc[0][3]);
                    acc[1][0] = fmaf(a0, b01.y, acc[1][0]);
                    acc[1][1] = fmaf(a1, b01.y, acc[1][1]);
                    acc[1][2] = fmaf(a2, b01.y, acc[1][2]);
                    acc[1][3] = fmaf(a3, b01.y, acc[1][3]);
                    acc[2][0] = fmaf(a0, b23.x, acc[2][0]);
                    acc[2][1] = fmaf(a1, b23.x, acc[2][1]);
                    acc[2][2] = fmaf(a2, b23.x, acc[2][2]);
                    acc[2][3] = fmaf(a3, b23.x, acc[2][3]);
                    acc[3][0] = fmaf(a0, b23.y, acc[3][0]);
                    acc[3][1] = fmaf(a1, b23.y, acc[3][1]);
                    acc[3][2] = fmaf(a2, b23.y, acc[3][2]);
                    acc[3][3] = fmaf(a3, b23.y, acc[3][3]);
                    acc[4][0] = fmaf(a0, b45.x, acc[4][0]);
                    acc[4][1] = fmaf(a1, b45.x, acc[4][1]);
                    acc[4][2] = fmaf(a2, b45.x, acc[4][2]);
                    acc[4][3] = fmaf(a3, b45.x, acc[4][3]);
                    acc[5][0] = fmaf(a0, b45.y, acc[5][0]);
                    acc[5][1] = fmaf(a1, b45.y, acc[5][1]);
                    acc[5][2] = fmaf(a2, b45.y, acc[5][2]);
                    acc[5][3] = fmaf(a3, b45.y, acc[5][3]);
                }
                if (c < 5) {                        // commit next chunk to other buffer
                    float* bD = &myB[((c + 1) & 1) * 3072];
#pragma unroll
                    for (int r = 0; r < 3; r++) {
                        int lin = t2 + r * 256;
                        int kk = lin / 24;
                        int nn = (lin % 24) << 2;
                        *(float4*)&bD[kk * 96 + nn] = bfr[r];
                    }
                }
                // group-scoped barrier: decouples the 3 k-groups' pipelines
                asm volatile("bar.sync %0, %1;" :: "r"(grp + 1), "r"(256) : "memory");
            }
        } else {
            __syncthreads();   // cover Cs/halo init before first epilogue use
        }

        // epilogue: each group writes its partial (grp0 folds hpre in)
#pragma unroll
        for (int j = 0; j < 6; j++) {
            float* d = &mySs[(ty * 6 + j) * 68 + tx];
            if (grp == 0) {
                d[0]  = acc[j][0] + pre[j][0];
                d[16] = acc[j][1] + pre[j][1];
                d[32] = acc[j][2] + pre[j][2];
                d[48] = acc[j][3] + pre[j][3];
            } else {
                d[0]  = acc[j][0];
                d[16] = acc[j][1];
                d[32] = acc[j][2];
                d[48] = acc[j][3];
            }
        }
        __syncthreads();

        // fused LSTM gates + cell update + h writeback (sum the three partials)
        float* outp = &g_outh[(size_t)((y * NB + bm) * FEAT + bn * 24) * NW];
#pragma unroll
        for (int r = 0; r < 2; r++) {
            int p = tid + r * 768;                  // 0..1535 = f_local*64 + w
            int fl = p >> 6;
            int w = p & 63;
            int i0 = (fl * 4 + 0) * 68 + w;
            int i1 = (fl * 4 + 1) * 68 + w;
            int i2 = (fl * 4 + 2) * 68 + w;
            int i3 = (fl * 4 + 3) * 68 + w;
            float so = sigm(Ss[i0] + Ss[6528 + i0] + Ss[13056 + i0]);
            float sf = sigm(Ss[i1] + Ss[6528 + i1] + Ss[13056 + i1]);
            float si = sigm(Ss[i2] + Ss[6528 + i2] + Ss[13056 + i2]);
            float sg = sigm(Ss[i3] + Ss[6528 + i3] + Ss[13056 + i3]);
            float c = fmaf(sf, Cs[p], si * sg);
            Cs[p] = c;
            outp[fl * NW + w] = so * tanhf(c);
        }
        __syncthreads();                            // Ss consumed before next row overwrites

        // inter-block barrier: all h of row y visible before any block starts row y+1
        if (y < NH - 1) {
            __threadfence();                        // every thread: flush its h stores
            __syncthreads();                        // all fences done before signaling
            if (tid == 0) {
                atomicAdd(&g_sync, 1);
                int target = NBLK * (y + 1);
                while (*(volatile int*)&g_sync < target) { }
            }
            __syncthreads();
        }
    }
}

// ---------------- phase 3: skip conv GEMM + residual, BM=128 BN=128 BK=16, 8x8 tiles ----------------
__global__ __launch_bounds__(256) void phase3_gemm(const float* __restrict__ x,
                                                   const float* __restrict__ b_skip,
                                                   float* __restrict__ out) {
    __shared__ float As[16][128];
    __shared__ float Bs[16][128];
    const int m0 = blockIdx.x * 128;    // m = (b*64+y)*64 + w
    const int n0 = blockIdx.y * 128;    // n = cin
    const int tid = threadIdx.x;
    const int tx = tid & 15;   // m dir: frags at m0+tx*4 and m0+64+tx*4
    const int ty = tid >> 4;   // n dir: owns n0+ty*8 .. +7

    float acc[2][4][8];
#pragma unroll
    for (int h = 0; h < 2; h++)
#pragma unroll
        for (int i = 0; i < 4; i++)
#pragma unroll
            for (int j = 0; j < 8; j++) acc[h][i][j] = 0.f;

    for (int k0 = 0; k0 < FEAT; k0 += 16) {
#pragma unroll
        for (int i = 0; i < 8; i++) {
            int idx = tid + i * 256;
            int kk = idx >> 7, mm = idx & 127;
            int m = m0 + mm;
            int w = m & 63, yy = (m >> 6) & 63, b = m >> 12;
            As[kk][mm] = g_outh[((size_t)((yy * NB + b) * FEAT) + k0 + kk) * NW + w];
        }
#pragma unroll
        for (int r = 0; r < 2; r++) {
            int lin = tid + r * 256;
            int kk = lin >> 5, nn4 = lin & 31;
            *(float4*)&Bs[kk][nn4 * 4] =
                *(const float4*)&g_wS[(size_t)(k0 + kk) * CIN + n0 + nn4 * 4];
        }
        __syncthreads();
#pragma unroll
        for (int k = 0; k < 16; k++) {
            float4 aA = *(const float4*)&As[k][tx * 4];
            float4 aB = *(const float4*)&As[k][64 + tx * 4];
            float4 b0 = *(const float4*)&Bs[k][ty * 8];
            float4 b1 = *(const float4*)&Bs[k][ty * 8 + 4];
            float av[2][4] = {{aA.x, aA.y, aA.z, aA.w}, {aB.x, aB.y, aB.z, aB.w}};
            float bb[8] = {b0.x, b0.y, b0.z, b0.w, b1.x, b1.y, b1.z, b1.w};
#pragma unroll
            for (int h = 0; h < 2; h++)
#pragma unroll
                for (int i = 0; i < 4; i++)
#pragma unroll
                    for (int j = 0; j < 8; j++)
                        acc[h][i][j] = fmaf(av[h][i], bb[j], acc[h][i][j]);
        }
        __syncthreads();
    }
#pragma unroll
    for (int h = 0; h < 2; h++) {
        int m = m0 + h * 64 + tx * 4;
        int w = m & 63, yy = (m >> 6) & 63, b = m >> 12;
#pragma unroll
        for (int j = 0; j < 8; j++) {
            int n = n0 + ty * 8 + j;
            size_t base = ((size_t)(b * CIN + n) * NH + yy) * NW + w;
            float4 xv = *(const float4*)&x[base];
            float bs = b_skip[n];
            float4 ov = make_float4(acc[h][0][j] + xv.x + bs,
                                    acc[h][1][j] + xv.y + bs,
                                    acc[h][2][j] + xv.z + bs,
                                    acc[h][3][j] + xv.w + bs);
            *(float4*)&out[base] = ov;
        }
    }
}

// ---------------- launch ----------------
extern "C" void kernel_launch(void* const* d_in, const int* in_sizes, int n_in,
                              void* d_out, int out_size) {
    const float* x = 0; const float* w_i2s = 0; const float* w_s2s = 0;
    const float* w_skip = 0; const float* b_skp = 0;
    for (int i = 0; i < n_in; i++) {
        switch (in_sizes[i]) {
            case NB * CIN * NH * NW:   x      = (const float*)d_in[i]; break;
            case CGATE * CIN * 3:      w_i2s  = (const float*)d_in[i]; break;
            case CGATE * FEAT * 3:     w_s2s  = (const float*)d_in[i]; break;
            case CIN * FEAT:           w_skip = (const float*)d_in[i]; break;
            case CIN:                  b_skp  = (const float*)d_in[i]; break;
        }
    }
    if (!x || !w_i2s || !w_s2s || !w_skip || !b_skp) {
        x      = (const float*)d_in[0];
        w_i2s  = (const float*)d_in[1];
        w_s2s  = (const float*)d_in[2];
        w_skip = (const float*)d_in[3];
        b_skp  = (const float*)d_in[4];
    }
    float* out = (float*)d_out;

    cudaFuncSetAttribute(recurrence, cudaFuncAttributeMaxDynamicSharedMemorySize, SMEM_BYTES);

    prep_weights<<<1024, 256>>>(w_i2s, w_s2s, w_skip);
    phase1_gemm<<<dim3(512, 6), 256>>>(x);
    recurrence<<<NBLK, 768, SMEM_BYTES>>>();
    phase3_gemm<<<dim3(512, 3), 256>>>(x, b_skp, out);
}

// round 16
// speedup vs baseline: 1.4094x; 1.4094x over previous
#include <cuda_runtime.h>

#define CIN   384
#define FEAT  192
#define CGATE 768
#define NB    16
#define NH    64
#define NW    64
#define NBLK  128     // persistent blocks: 16 batch-tiles x 8 gate-col tiles

#define SLAB_STRIDE 72
// dynamic smem layout (floats) for recurrence (512 threads, 2 k-groups) — R13 config:
//   slab : 192*72                 = 13824
//   Bsm  : 2 grp * 2 buf * 32*96  = 12288
//   Ss   : 2 grp * 96*68          = 13056
//   Cs   : 24*64                  =  1536
#define SMEM_FLOATS (13824 + 12288 + 13056 + 1536)
#define SMEM_BYTES  (SMEM_FLOATS * 4)

// ---------------- device scratch ----------------
__device__ float g_hpre[(size_t)NH * NB * NW * CGATE];  // [m][n'] n' = f*4 + gate
__device__ float g_outh[(size_t)NH * NB * FEAT * NW];   // [y][b][f][w]
__device__ float g_wA[CIN * 2 * CGATE];                 // i2s masked+shuffled, cols n'=f*4+q
__device__ float g_wR[FEAT * 3 * CGATE];                // s2s, rows k=kw*192+ci, cols n'=f*4+q
__device__ float g_wS[FEAT * CIN];                      // skip masked, [f][cin]
__device__ int   g_sync;                                // inter-block barrier counter

// ---------------- weight prep ----------------
__global__ void prep_weights(const float* __restrict__ w_i2s,
                             const float* __restrict__ w_s2s,
                             const float* __restrict__ w_skip) {
    int stride = gridDim.x * blockDim.x;
    int t0 = blockIdx.x * blockDim.x + threadIdx.x;
    if (t0 == 0) g_sync = 0;                       // reset barrier each launch

    // g_wA: [k=ci*2+tap][n'=f*4+q]; shuffled source channel cg = g*256 + q*64 + r
    for (int i = t0; i < CIN * 2 * CGATE; i += stride) {
        int k = i / CGATE, np = i % CGATE;
        int ci = k >> 1, tap = k & 1;
        int q = np & 3, f = np >> 2;
        int g = f >> 6, r = f & 63;
        int cg = g * 256 + q * 64 + r;
        float v = w_i2s[(cg * CIN + ci) * 3 + tap];
        if (tap == 1 && g < (ci >> 7)) v = 0.f;    // center tap mask; right tap dropped
        g_wA[i] = v;
    }
    // g_wR: [k=kw*192+ci][n'=f*4+q]
    for (int i = t0; i < FEAT * 3 * CGATE; i += stride) {
        int k = i / CGATE, np = i % CGATE;
        int kw = k / 192, ci = k - kw * 192;
        int q = np & 3, f = np >> 2;
        g_wR[i] = w_s2s[((q * 192 + f) * FEAT + ci) * 3 + kw];
    }
    // g_wS: masked 1x1 skip, transposed to [f][cin]
    for (int i = t0; i < FEAT * CIN; i += stride) {
        int f = i / CIN, c = i % CIN;
        g_wS[i] = ((c >> 7) >= (f >> 6)) ? w_skip[c * FEAT + f] : 0.f;
    }
}

// ---------------- phase 1: input conv GEMM via mma.sync tf32 ----------------
// BM=128 BN=128 BK=32, 256 thr = 8 warps (2m x 4n), warp tile 64x32 of m16n8k8.
__device__ __forceinline__ unsigned f2tf(float f) {
    unsigned r;
    asm("cvt.rna.tf32.f32 %0, %1;" : "=r"(r) : "f"(f));
    return r;
}

#define AS_STRIDE 136   // (8*tg + g) mod 32 hits all banks -> conflict-free frags

__global__ __launch_bounds__(256) void phase1_gemm(const float* __restrict__ x) {
    __shared__ unsigned As[32][AS_STRIDE];   // [k][m]
    __shared__ unsigned Bs[32][AS_STRIDE];   // [k][n]
    const int m0 = blockIdx.x * 128;
    const int n0 = blockIdx.y * 128;
    const int tid = threadIdx.x;
    const int warp = tid >> 5, lane = tid & 31;
    const int wm = warp & 1, wn = warp >> 1;     // 2 x 4 warp grid
    const int g = lane >> 2, tg = lane & 3;

    float d[4][4][4];                            // [mi][ni][frag]
#pragma unroll
    for (int mi = 0; mi < 4; mi++)
#pragma unroll
        for (int ni = 0; ni < 4; ni++)
#pragma unroll
            for (int r = 0; r < 4; r++) d[mi][ni][r] = 0.f;

    for (int k0 = 0; k0 < CIN * 2; k0 += 32) {
        // A tile: 32k x 128m im2col gather + cvt (16 scalars/thread)
#pragma unroll
        for (int i = 0; i < 16; i++) {
            int idx = tid + i * 256;             // 0..4095
            int kk = idx >> 7, mm = idx & 127;
            int m = m0 + mm;
            int w = m & 63, b = (m >> 6) & 15, y = m >> 10;
            int kg = k0 + kk;
            int ci = kg >> 1, tap = kg & 1;
            int xw = w + tap - 1;
            float v = 0.f;
            if (xw >= 0) v = x[((b * CIN + ci) * NH + y) * NW + xw];
            As[kk][mm] = f2tf(v);
        }
        // B tile: 32k x 128n, vectorized + cvt (4 float4/thread)
#pragma unroll
        for (int r = 0; r < 4; r++) {
            int lin = tid + r * 256;             // float4 index, 1024 total
            int kk = lin >> 5, nn4 = lin & 31;
            float4 v = *(const float4*)&g_wA[(size_t)(k0 + kk) * CGATE + n0 + nn4 * 4];
            unsigned* dst = &Bs[kk][nn4 * 4];
            dst[0] = f2tf(v.x); dst[1] = f2tf(v.y);
            dst[2] = f2tf(v.z); dst[3] = f2tf(v.w);
        }
        __syncthreads();

#pragma unroll
        for (int ks = 0; ks < 32; ks += 8) {
            unsigned a[4][4], bfr[4][2];
#pragma unroll
            for (int mi = 0; mi < 4; mi++) {
                int rb = wm * 64 + mi * 16;
                a[mi][0] = As[ks + tg][rb + g];
                a[mi][1] = As[ks + tg][rb + g + 8];
                a[mi][2] = As[ks + tg + 4][rb + g];
                a[mi][3] = As[ks + tg + 4][rb + g + 8];
            }
#pragma unroll
            for (int ni = 0; ni < 4; ni++) {
                int nb = wn * 32 + ni * 8;
                bfr[ni][0] = Bs[ks + tg][nb + g];
                bfr[ni][1] = Bs[ks + tg + 4][nb + g];
            }
#pragma unroll
            for (int mi = 0; mi < 4; mi++)
#pragma unroll
                for (int ni = 0; ni < 4; ni++)
                    asm volatile(
                        "mma.sync.aligned.m16n8k8.row.col.f32.tf32.tf32.f32 "
                        "{%0,%1,%2,%3}, {%4,%5,%6,%7}, {%8,%9}, {%0,%1,%2,%3};"
                        : "+f"(d[mi][ni][0]), "+f"(d[mi][ni][1]),
                          "+f"(d[mi][ni][2]), "+f"(d[mi][ni][3])
                        : "r"(a[mi][0]), "r"(a[mi][1]), "r"(a[mi][2]), "r"(a[mi][3]),
                          "r"(bfr[ni][0]), "r"(bfr[ni][1]));
        }
        __syncthreads();
    }

    // epilogue: fragment -> g_hpre (float2 stores)
#pragma unroll
    for (int mi = 0; mi < 4; mi++) {
        int m = m0 + wm * 64 + mi * 16 + g;
#pragma unroll
        for (int ni = 0; ni < 4; ni++) {
            int n = n0 + wn * 32 + ni * 8 + tg * 2;
            *(float2*)&g_hpre[(size_t)m * CGATE + n] =
                make_float2(d[mi][ni][0], d[mi][ni][1]);
            *(float2*)&g_hpre[(size_t)(m + 8) * CGATE + n] =
                make_float2(d[mi][ni][2], d[mi][ni][3]);
        }
    }
}

// ---------------- phase 2: persistent fused recurrence, 512 thr, K-split x2 (R13) ----------------
__device__ __forceinline__ float sigm(float v) { return 1.f / (1.f + __expf(-v)); }

__global__ __launch_bounds__(512, 1) void recurrence() {
    extern __shared__ float sm[];
    float* slab = sm;                       // 192 x 72
    float* Bsm  = sm + 13824;               // 2 grp x 2 buf x 3072
    float* Ss   = sm + 13824 + 12288;       // 2 grp x 6528
    float* Cs   = sm + 13824 + 12288 + 13056; // 24 x 64

    const int tid = threadIdx.x;
    const int grp = tid >> 8;               // k-split group (warp-uniform)
    const int t2  = tid & 255;
    const int tx  = t2 & 15;                // m-lane: owns m = tx + 16*i
    const int ty  = t2 >> 4;                // n-lane: owns n' = ty*6 .. +5
    const int bm  = blockIdx.x & 15;        // batch b
    const int bn  = blockIdx.x >> 4;        // 0..7, n0 = bn*96
    const int n0  = bn * 96;
    const int kc0 = grp * 9;                // my chunk range: kc0 .. kc0+8

    float* myB  = Bsm + grp * 6144;
    float* mySs = Ss + grp * 6528;

    // one-time init (first use is after a __syncthreads)
    for (int p = tid; p < 1536; p += 512) Cs[p] = 0.f;
    if (tid < 192) { slab[tid * SLAB_STRIDE] = 0.f; slab[tid * SLAB_STRIDE + 65] = 0.f; }

    for (int y = 0; y < NH; y++) {
        // group 0 prefetches hpre tile into regs (added at its Ss write)
        float pre[6][4];
        if (grp == 0) {
            size_t mb = (size_t)(y * NB + bm) * NW;
#pragma unroll
            for (int i = 0; i < 4; i++) {
                const float* p = &g_hpre[(mb + tx + i * 16) * CGATE + n0 + ty * 6];
                float2 v0 = *(const float2*)(p);
                float2 v1 = *(const float2*)(p + 2);
                float2 v2 = *(const float2*)(p + 4);
                pre[0][i] = v0.x; pre[1][i] = v0.y;
                pre[2][i] = v1.x; pre[3][i] = v1.y;
                pre[4][i] = v2.x; pre[5][i] = v2.y;
            }
        }

        float acc[6][4];
#pragma unroll
        for (int j = 0; j < 6; j++)
#pragma unroll
            for (int i = 0; i < 4; i++) acc[j][i] = 0.f;

        if (y > 0) {
            // slab: h_{y-1}[192][64] into smem (512 threads, 6 float4 each)
            const float* hp = &g_outh[(size_t)((y - 1) * NB + bm) * FEAT * NW];
#pragma unroll
            for (int r = 0; r < 6; r++) {
                int lin = tid + r * 512;            // float4 index 0..3071
                int f = lin >> 4;
                int w4 = (lin & 15) << 2;
                float4 v = *(const float4*)&hp[f * NW + w4];
                float* d = &slab[f * SLAB_STRIDE + 1 + w4];
                d[0] = v.x; d[1] = v.y; d[2] = v.z; d[3] = v.w;
            }
            // preload my group's chunk kc0
            float4 bfr[3];
#pragma unroll
            for (int r = 0; r < 3; r++) {
                int lin = t2 + r * 256;             // 0..767 float4
                int kk = lin / 24;
                int nn = (lin % 24) << 2;
                bfr[r] = *(const float4*)&g_wR[(size_t)(kc0 * 32 + kk) * CGATE + n0 + nn];
            }
#pragma unroll
            for (int r = 0; r < 3; r++) {
                int lin = t2 + r * 256;
                int kk = lin / 24;
                int nn = (lin % 24) << 2;
                *(float4*)&myB[kk * 96 + nn] = bfr[r];
            }
            __syncthreads();

            for (int c = 0; c < 9; c++) {
                int kc = kc0 + c;
                if (c < 8) {                        // prefetch next chunk
#pragma unroll
                    for (int r = 0; r < 3; r++) {
                        int lin = t2 + r * 256;
                        int kk = lin / 24;
                        int nn = (lin % 24) << 2;
                        bfr[r] = *(const float4*)&g_wR[(size_t)((kc + 1) * 32 + kk) * CGATE + n0 + nn];
                    }
                }
                // k = kw*192 + ci ordering: kw uniform per chunk -> A addr is base + kk*72
                int kw  = kc / 6;
                int ci0 = (kc - kw * 6) * 32;
                const float* aP = &slab[ci0 * SLAB_STRIDE + tx + kw];
                const float* bP = &myB[(c & 1) * 3072 + ty * 6];
#pragma unroll
                for (int kk = 0; kk < 32; kk++) {
                    float a0 = aP[kk * SLAB_STRIDE + 0];
                    float a1 = aP[kk * SLAB_STRIDE + 16];
                    float a2 = aP[kk * SLAB_STRIDE + 32];
                    float a3 = aP[kk * SLAB_STRIDE + 48];
                    float2 b01 = *(const float2*)&bP[kk * 96 + 0];
                    float2 b23 = *(const float2*)&bP[kk * 96 + 2];
                    float2 b45 = *(const float2*)&bP[kk * 96 + 4];
                    acc[0][0] = fmaf(a0, b01.x, acc[0][0]);
                    acc[0][1] = fmaf(a1, b01.x, acc[0][1]);
                    acc[0][2] = fmaf(a2, b01.x, acc[0][2]);
                    acc[0][3] = fmaf(a3, b01.x, acc[0][3]);
                    acc[1][0] = fmaf(a0, b01.y, acc[1][0]);
                    acc[1][1] = fmaf(a1, b01.y, acc[1][1]);
                    acc[1][2] = fmaf(a2, b01.y, acc[1][2]);
                    acc[1][3] = fmaf(a3, b01.y, acc[1][3]);
                    acc[2][0] = fmaf(a0, b23.x, acc[2][0]);
                    acc[2][1] = fmaf(a1, b23.x, acc[2][1]);
                    acc[2][2] = fmaf(a2, b23.x, acc[2][2]);
                    acc[2][3] = fmaf(a3, b23.x, acc[2][3]);
                    acc[3][0] = fmaf(a0, b23.y, acc[3][0]);
                    acc[3][1] = fmaf(a1, b23.y, acc[3][1]);
                    acc[3][2] = fmaf(a2, b23.y, acc[3][2]);
                    acc[3][3] = fmaf(a3, b23.y, acc[3][3]);
                    acc[4][0] = fmaf(a0, b45.x, acc[4][0]);
                    acc[4][1] = fmaf(a1, b45.x, acc[4][1]);
                    acc[4][2] = fmaf(a2, b45.x, acc[4][2]);
                    acc[4][3] = fmaf(a3, b45.x, acc[4][3]);
                    acc[5][0] = fmaf(a0, b45.y, acc[5][0]);
                    acc[5][1] = fmaf(a1, b45.y, acc[5][1]);
                    acc[5][2] = fmaf(a2, b45.y, acc[5][2]);
                    acc[5][3] = fmaf(a3, b45.y, acc[5][3]);
                }
                if (c < 8) {                        // commit next chunk to other buffer
                    float* bD = &myB[((c + 1) & 1) * 3072];
#pragma unroll
                    for (int r = 0; r < 3; r++) {
                        int lin = t2 + r * 256;
                        int kk = lin / 24;
                        int nn = (lin % 24) << 2;
                        *(float4*)&bD[kk * 96 + nn] = bfr[r];
                    }
                }
                __syncthreads();
            }
        } else {
            __syncthreads();   // cover Cs/halo init before first epilogue use
        }

        // epilogue: each group writes its partial (grp0 folds hpre in)
#pragma unroll
        for (int j = 0; j < 6; j++) {
            float* d = &mySs[(ty * 6 + j) * 68 + tx];
            if (grp == 0) {
                d[0]  = acc[j][0] + pre[j][0];
                d[16] = acc[j][1] + pre[j][1];
                d[32] = acc[j][2] + pre[j][2];
                d[48] = acc[j][3] + pre[j][3];
            } else {
                d[0]  = acc[j][0];
                d[16] = acc[j][1];
                d[32] = acc[j][2];
                d[48] = acc[j][3];
            }
        }
        __syncthreads();

        // fused LSTM gates + cell update + h writeback (sum the two partials)
        float* outp = &g_outh[(size_t)((y * NB + bm) * FEAT + bn * 24) * NW];
#pragma unroll
        for (int r = 0; r < 3; r++) {
            int p = tid + r * 512;                  // 0..1535 = f_local*64 + w
            int fl = p >> 6;
            int w = p & 63;
            float so = sigm(Ss[(fl * 4 + 0) * 68 + w] + Ss[6528 + (fl * 4 + 0) * 68 + w]);
            float sf = sigm(Ss[(fl * 4 + 1) * 68 + w] + Ss[6528 + (fl * 4 + 1) * 68 + w]);
            float si = sigm(Ss[(fl * 4 + 2) * 68 + w] + Ss[6528 + (fl * 4 + 2) * 68 + w]);
            float sg = sigm(Ss[(fl * 4 + 3) * 68 + w] + Ss[6528 + (fl * 4 + 3) * 68 + w]);
            float c = fmaf(sf, Cs[p], si * sg);
            Cs[p] = c;
            outp[fl * NW + w] = so * tanhf(c);
        }
        __syncthreads();                            // Ss consumed before next row overwrites

        // inter-block barrier: all h of row y visible before any block starts row y+1
        if (y < NH - 1) {
            __threadfence();                        // every thread: flush its h stores
            __syncthreads();                        // all fences done before signaling
            if (tid == 0) {
                atomicAdd(&g_sync, 1);
                int target = NBLK * (y + 1);
                while (*(volatile int*)&g_sync < target) { }
            }
            __syncthreads();
        }
    }
}

// ---------------- phase 3: skip conv GEMM + residual, BM=128 BN=128 BK=16, 8x8 tiles ----------------
__global__ __launch_bounds__(256) void phase3_gemm(const float* __restrict__ x,
                                                   const float* __restrict__ b_skip,
                                                   float* __restrict__ out) {
    __shared__ float As[16][128];
    __shared__ float Bs[16][128];
    const int m0 = blockIdx.x * 128;    // m = (b*64+y)*64 + w
    const int n0 = blockIdx.y * 128;    // n = cin
    const int tid = threadIdx.x;
    const int tx = tid & 15;   // m dir: frags at m0+tx*4 and m0+64+tx*4
    const int ty = tid >> 4;   // n dir: owns n0+ty*8 .. +7

    float acc[2][4][8];
#pragma unroll
    for (int h = 0; h < 2; h++)
#pragma unroll
        for (int i = 0; i < 4; i++)
#pragma unroll
            for (int j = 0; j < 8; j++) acc[h][i][j] = 0.f;

    for (int k0 = 0; k0 < FEAT; k0 += 16) {
#pragma unroll
        for (int i = 0; i < 8; i++) {
            int idx = tid + i * 256;
            int kk = idx >> 7, mm = idx & 127;
            int m = m0 + mm;
            int w = m & 63, yy = (m >> 6) & 63, b = m >> 12;
            As[kk][mm] = g_outh[((size_t)((yy * NB + b) * FEAT) + k0 + kk) * NW + w];
        }
#pragma unroll
        for (int r = 0; r < 2; r++) {
            int lin = tid + r * 256;
            int kk = lin >> 5, nn4 = lin & 31;
            *(float4*)&Bs[kk][nn4 * 4] =
                *(const float4*)&g_wS[(size_t)(k0 + kk) * CIN + n0 + nn4 * 4];
        }
        __syncthreads();
#pragma unroll
        for (int k = 0; k < 16; k++) {
            float4 aA = *(const float4*)&As[k][tx * 4];
            float4 aB = *(const float4*)&As[k][64 + tx * 4];
            float4 b0 = *(const float4*)&Bs[k][ty * 8];
            float4 b1 = *(const float4*)&Bs[k][ty * 8 + 4];
            float av[2][4] = {{aA.x, aA.y, aA.z, aA.w}, {aB.x, aB.y, aB.z, aB.w}};
            float bb[8] = {b0.x, b0.y, b0.z, b0.w, b1.x, b1.y, b1.z, b1.w};
#pragma unroll
            for (int h = 0; h < 2; h++)
#pragma unroll
                for (int i = 0; i < 4; i++)
#pragma unroll
                    for (int j = 0; j < 8; j++)
                        acc[h][i][j] = fmaf(av[h][i], bb[j], acc[h][i][j]);
        }
        __syncthreads();
    }
#pragma unroll
    for (int h = 0; h < 2; h++) {
        int m = m0 + h * 64 + tx * 4;
        int w = m & 63, yy = (m >> 6) & 63, b = m >> 12;
#pragma unroll
        for (int j = 0; j < 8; j++) {
            int n = n0 + ty * 8 + j;
            size_t base = ((size_t)(b * CIN + n) * NH + yy) * NW + w;
            float4 xv = *(const float4*)&x[base];
            float bs = b_skip[n];
            float4 ov = make_float4(acc[h][0][j] + xv.x + bs,
                                    acc[h][1][j] + xv.y + bs,
                                    acc[h][2][j] + xv.z + bs,
                                    acc[h][3][j] + xv.w + bs);
            *(float4*)&out[base] = ov;
        }
    }
}

// ---------------- launch ----------------
extern "C" void kernel_launch(void* const* d_in, const int* in_sizes, int n_in,
                              void* d_out, int out_size) {
    const float* x = 0; const float* w_i2s = 0; const float* w_s2s = 0;
    const float* w_skip = 0; const float* b_skp = 0;
    for (int i = 0; i < n_in; i++) {
        switch (in_sizes[i]) {
            case NB * CIN * NH * NW:   x      = (const float*)d_in[i]; break;
            case CGATE * CIN * 3:      w_i2s  = (const float*)d_in[i]; break;
            case CGATE * FEAT * 3:     w_s2s  = (const float*)d_in[i]; break;
            case CIN * FEAT:           w_skip = (const float*)d_in[i]; break;
            case CIN:                  b_skp  = (const float*)d_in[i]; break;
        }
    }
    if (!x || !w_i2s || !w_s2s || !w_skip || !b_skp) {
        x      = (const float*)d_in[0];
        w_i2s  = (const float*)d_in[1];
        w_s2s  = (const float*)d_in[2];
        w_skip = (const float*)d_in[3];
        b_skp  = (const float*)d_in[4];
    }
    float* out = (float*)d_out;

    cudaFuncSetAttribute(recurrence, cudaFuncAttributeMaxDynamicSharedMemorySize, SMEM_BYTES);

    prep_weights<<<1024, 256>>>(w_i2s, w_s2s, w_skip);
    phase1_gemm<<<dim3(512, 6), 256>>>(x);
    recurrence<<<NBLK, 512, SMEM_BYTES>>>();
    phase3_gemm<<<dim3(512, 3), 256>>>(x, b_skp, out);
}